// round 15
// baseline (speedup 1.0000x reference)
#include <cuda_runtime.h>
#include <cstdint>

#define D_MODEL   512
#define BATCH     128
#define NATOM     512
#define M_TOT     (BATCH * NATOM)
#define NEXP      8
#define NELEM     4
#define NCHG      3
#define NCOMBO    12

#define SLICES    24          // grid.x -> 288 blocks = one wave at 2 blocks/SM
#define TPB       128
#define WARPS_PB  (TPB / 32)
#define NBLOCKS   (SLICES * NCOMBO)

typedef unsigned long long ull;

// ---------------- device scratch (zero-initialized at module load; the last
// main-kernel block re-zeros everything so each replay sees clean state) ----
__device__ float g_wgT[NEXP * D_MODEL];          // Wg transposed: [x][d]
__device__ float g_gate[BATCH * NEXP];
__device__ float g_eo[BATCH * NEXP];
__device__ int   g_count[NCOMBO];
__device__ int   g_done;
__device__ int   g_idx[NCOMBO][M_TOT];

// ---------------- packed f32x2 helpers ----------------
__device__ __forceinline__ void fma2(ull& d, ull a, ull b) {
    asm("fma.rn.f32x2 %0, %1, %2, %0;" : "+l"(d) : "l"(a), "l"(b));
}
__device__ __forceinline__ float upk_sum(ull v) {
    float a, b;
    asm("mov.b64 {%0, %1}, %2;" : "=f"(a), "=f"(b) : "l"(v));
    return a + b;
}

// ---------------- compaction (block-aggregated) + Wg transpose -------------
__global__ void compact_kernel(const int* __restrict__ E,
                               const int* __restrict__ C,
                               const float* __restrict__ Wg) {
    __shared__ int scnt[NCOMBO];
    __shared__ int sbase[NCOMBO];
    const int tid = threadIdx.x;
    const int i = blockIdx.x * blockDim.x + tid;     // exactly M_TOT threads
    if (tid < NCOMBO) scnt[tid] = 0;
    __syncthreads();

    const int combo = E[i] * NCHG + C[i];
    unsigned mask = __match_any_sync(0xffffffffu, combo);
    const int lane = tid & 31;
    const int leader = __ffs(mask) - 1;
    int wbase = 0;
    if (lane == leader) wbase = atomicAdd(&scnt[combo], __popc(mask));
    wbase = __shfl_sync(mask, wbase, leader);
    const int pos = wbase + __popc(mask & ((1u << lane) - 1));
    __syncthreads();

    if (tid < NCOMBO) sbase[tid] = atomicAdd(&g_count[tid], scnt[tid]);
    __syncthreads();
    g_idx[combo][sbase[combo] + pos] = i;

    if (blockIdx.x == 0) {
        for (int j = tid; j < NEXP * D_MODEL; j += blockDim.x) {
            int x = j >> 9;
            int d = j & 511;
            g_wgT[x * D_MODEL + d] = Wg[d * NEXP + x];
        }
    }
}

// ---------------- 7-shuffle tree reduce across the 8 intra-octet lanes -----
// v[0..7] per-lane partials of 8 flat slots; lane l (= lane&7) gets slot l.
__device__ __forceinline__ float reduce8(const float* v, int l) {
    const bool b0 = l & 1, b1 = l & 2, b2 = l & 4;
    float n0 = (b0 ? v[1] : v[0]) + __shfl_xor_sync(0xffffffffu, b0 ? v[0] : v[1], 1);
    float n1 = (b0 ? v[3] : v[2]) + __shfl_xor_sync(0xffffffffu, b0 ? v[2] : v[3], 1);
    float n2 = (b0 ? v[5] : v[4]) + __shfl_xor_sync(0xffffffffu, b0 ? v[4] : v[5], 1);
    float n3 = (b0 ? v[7] : v[6]) + __shfl_xor_sync(0xffffffffu, b0 ? v[6] : v[7], 1);
    float m0 = (b1 ? n1 : n0) + __shfl_xor_sync(0xffffffffu, b1 ? n0 : n1, 2);
    float m1 = (b1 ? n3 : n2) + __shfl_xor_sync(0xffffffffu, b1 ? n2 : n3, 2);
    return (b2 ? m1 : m0) + __shfl_xor_sync(0xffffffffu, b2 ? m0 : m1, 4);
}

// ---------------- main kernel (fused finalize) ----------------
// Lane = g*8 + l: g = ROW-CLASS (rows rg*4+g) / LDS phase-octet,
//                 l = d-subchunk (16B of a 128B slice).
// EIGHT atoms per warp-pass: every weight LDS.128 (512 distinct bytes, 4
// conflict-free phases) now feeds 8 atoms -> 6 KB weight smem per atom
// (halved vs R14). acc[6 row-classes][8 atoms] f32x2 partials; X streams
// via a depth-2 rotating buffer.
__global__ __launch_bounds__(TPB, 2)
void moe_main_kernel(const float* __restrict__ X,
                     const float* __restrict__ We,
                     const float* __restrict__ Wc,
                     const float* __restrict__ bg,
                     const float* __restrict__ be,
                     const float* __restrict__ bc,
                     float* __restrict__ out) {
    __shared__ __align__(16) float sw[24 * D_MODEL];   // 48 KB
    __shared__ int s_last;

    const int combo = blockIdx.y;
    const int El = combo / NCHG;
    const int Cl = combo - El * NCHG;
    const int tid = threadIdx.x;

    // Weight tile: rows 0-7 gate (g_wgT), 8-15 We[x][El], 16-23 Wc[x][Cl]
    {
        const float4* wg4 = reinterpret_cast<const float4*>(g_wgT);
        float4* sw4 = reinterpret_cast<float4*>(sw);
#pragma unroll
        for (int i = tid; i < NEXP * (D_MODEL / 4); i += TPB)
            sw4[i] = wg4[i];
#pragma unroll
        for (int i = tid; i < NEXP * (D_MODEL / 4); i += TPB) {
            int x = i / (D_MODEL / 4);
            int c = i % (D_MODEL / 4);
            reinterpret_cast<float4*>(sw + (8 + x) * D_MODEL)[c] =
                reinterpret_cast<const float4*>(We + (size_t)(x * NELEM + El) * D_MODEL)[c];
            reinterpret_cast<float4*>(sw + (16 + x) * D_MODEL)[c] =
                reinterpret_cast<const float4*>(Wc + (size_t)(x * NCHG + Cl) * D_MODEL)[c];
        }
    }
    __syncthreads();

    const int L = g_count[combo];
    const int wid  = tid >> 5;
    const int lane = tid & 31;
    const int g = lane >> 3;          // row-class / LDS phase octet
    const int l = lane & 7;           // d-subchunk within a 128B slice
    const int a_mine = l & 3;         // first atom this lane reports (A half)
    const int x_mine = ((l >> 2) << 2) + g;   // expert this lane reports
    const int* __restrict__ idxp = g_idx[combo];
    const int warps_tot = SLICES * WARPS_PB;  // 96 per combo

    // per-lane weight base: w(rg, s) at swl[rg*512 + s*8] (ulonglong2 units)
    const ulonglong2* __restrict__ swl =
        reinterpret_cast<const ulonglong2*>(sw) + g * 128 + l;

    const float bgx = __ldg(bg + x_mine);
    const float bex = __ldg(be + x_mine * NELEM + El);
    const float bcx = __ldg(bc + x_mine * NCHG + Cl);

    for (int t = blockIdx.x * WARPS_PB + wid; t * 8 < L; t += warps_tot) {
        const int i0 = t * 8;
        int  m[8];
        bool act[8];
#pragma unroll
        for (int a = 0; a < 8; a++) {
            act[a] = (i0 + a < L);
            m[a] = idxp[act[a] ? i0 + a : 0];
        }
        const ulonglong2* xp[8];
#pragma unroll
        for (int a = 0; a < 8; a++)
            xp[a] = reinterpret_cast<const ulonglong2*>(X + (size_t)m[a] * D_MODEL) + l;

        ull acc[6][8];
#pragma unroll
        for (int rg = 0; rg < 6; rg++)
#pragma unroll
            for (int a = 0; a < 8; a++) acc[rg][a] = 0ull;

        // depth-2 rotating X buffer
        ulonglong2 xb[2][8];
#pragma unroll
        for (int s = 0; s < 2; s++)
#pragma unroll
            for (int a = 0; a < 8; a++) xb[s][a] = xp[a][s * 8];

#pragma unroll
        for (int s = 0; s < 16; s++) {
            const int slot = s & 1;
#pragma unroll
            for (int rg = 0; rg < 6; rg++) {
                const ulonglong2 w = swl[rg * 512 + s * 8];
#pragma unroll
                for (int a = 0; a < 8; a++) {
                    fma2(acc[rg][a], xb[slot][a].x, w.x);
                    fma2(acc[rg][a], xb[slot][a].y, w.y);
                }
            }
            if (s + 2 < 16) {
#pragma unroll
                for (int a = 0; a < 8; a++) xb[slot][a] = xp[a][(s + 2) * 8];
            }
        }

        // ---- epilogue: two halves (atoms 0-3 = A, atoms 4-7 = B) ----
        // flat slot f = (rg_local<<2) | a ; lane l ends with slot l
        float vgA[8], vpA[8], vcA[8], vgB[8], vpB[8], vcB[8];
#pragma unroll
        for (int f = 0; f < 8; f++) {
            const int rgl = f >> 2, a = f & 3;
            vgA[f] = upk_sum(acc[rgl][a]);
            vgB[f] = upk_sum(acc[rgl][4 + a]);
            vpA[f] = upk_sum(acc[2 + rgl][a]);
            vpB[f] = upk_sum(acc[2 + rgl][4 + a]);
            vcA[f] = upk_sum(acc[4 + rgl][a]);
            vcB[f] = upk_sum(acc[4 + rgl][4 + a]);
        }
        // lane (g,l): atom a_mine(+4), expert x_mine; rows x, 8+x, 16+x
        float glA = reduce8(vgA, l) + bgx;
        float peA = reduce8(vpA, l) + bex;
        float pcA = reduce8(vcA, l) + bcx;
        float glB = reduce8(vgB, l) + bgx;
        float peB = reduce8(vpB, l) + bex;
        float pcB = reduce8(vcB, l) + bcx;

        // softmax over the 8 experts of each atom: lanes differ by xor 4,8,16
        float mxA = glA, mxB = glB;
#pragma unroll
        for (int k = 4; k <= 16; k <<= 1) {
            mxA = fmaxf(mxA, __shfl_xor_sync(0xffffffffu, mxA, k));
            mxB = fmaxf(mxB, __shfl_xor_sync(0xffffffffu, mxB, k));
        }
        float eA = __expf(glA - mxA), eB = __expf(glB - mxB);
        float sA = eA, sB = eB;
#pragma unroll
        for (int k = 4; k <= 16; k <<= 1) {
            sA += __shfl_xor_sync(0xffffffffu, sA, k);
            sB += __shfl_xor_sync(0xffffffffu, sB, k);
        }

        // select this lane's atoms (a_mine and a_mine+4)
        const int  mA  = (a_mine & 2) ? ((a_mine & 1) ? m[3] : m[2])
                                      : ((a_mine & 1) ? m[1] : m[0]);
        const bool acA = (a_mine & 2) ? ((a_mine & 1) ? act[3] : act[2])
                                      : ((a_mine & 1) ? act[1] : act[0]);
        const int  mB  = (a_mine & 2) ? ((a_mine & 1) ? m[7] : m[6])
                                      : ((a_mine & 1) ? m[5] : m[4]);
        const bool acB = (a_mine & 2) ? ((a_mine & 1) ? act[7] : act[6])
                                      : ((a_mine & 1) ? act[5] : act[4]);
        if (acA) {
            const int b = mA >> 9;                 // N = 512
            atomicAdd(&g_gate[b * NEXP + x_mine], eA / sA);
            atomicAdd(&g_eo[b * NEXP + x_mine], peA * fabsf(pcA));
        }
        if (acB) {
            const int b = mB >> 9;
            atomicAdd(&g_gate[b * NEXP + x_mine], eB / sB);
            atomicAdd(&g_eo[b * NEXP + x_mine], peB * fabsf(pcB));
        }
    }

    // ---- fused finalize: last block computes output + cleans scratch ----
    __threadfence();
    if (tid == 0) {
        int n = atomicAdd(&g_done, 1);
        s_last = (n == NBLOCKS - 1) ? 1 : 0;
    }
    __syncthreads();
    if (s_last) {
        int b = tid;               // TPB == BATCH == 128
        float s = 0.f;
#pragma unroll
        for (int x = 0; x < NEXP; x++)
            s += __ldcg(&g_gate[b * NEXP + x]) * __ldcg(&g_eo[b * NEXP + x]);
        out[b] = -s;
#pragma unroll
        for (int x = 0; x < NEXP; x++) {
            g_gate[b * NEXP + x] = 0.f;
            g_eo[b * NEXP + x]   = 0.f;
        }
        if (tid < NCOMBO) g_count[tid] = 0;
        if (tid == 0) g_done = 0;
    }
}

// ---------------- launch ----------------
extern "C" void kernel_launch(void* const* d_in, const int* in_sizes, int n_in,
                              void* d_out, int out_size) {
    const float* X  = (const float*)d_in[0];
    const int*   E  = (const int*)d_in[1];
    const int*   C  = (const int*)d_in[2];
    const float* Wg = (const float*)d_in[3];
    const float* bg = (const float*)d_in[4];
    const float* We = (const float*)d_in[5];
    const float* be = (const float*)d_in[6];
    const float* Wc = (const float*)d_in[7];
    const float* bc = (const float*)d_in[8];

    compact_kernel<<<M_TOT / 256, 256>>>(E, C, Wg);
    moe_main_kernel<<<dim3(SLICES, NCOMBO), TPB>>>(X, We, Wc, bg, be, bc,
                                                   (float*)d_out);
}